// round 1
// baseline (speedup 1.0000x reference)
#include <cuda_runtime.h>

#define H        1024
#define S        32768
#define THREADS  256
#define WARPS    (THREADS / 32)
#define GRID     256
#define VEC      8            // 8 x float4 per thread per row (32 floats)

__global__ void zero_out_kernel(float* __restrict__ out) {
    int i = blockIdx.x * blockDim.x + threadIdx.x;
    if (i < H) out[i] = 0.0f;
}

__global__ __launch_bounds__(THREADS, 2)
void bahdanau_cos_kernel(const float* __restrict__ query,
                         const float* __restrict__ keys,
                         float* __restrict__ out) {
    __shared__ float s_ctx[H];

    const int tid  = threadIdx.x;
    const int lane = tid & 31;
    const int warp = tid >> 5;

    // zero shared context accumulator
    for (int i = tid; i < H; i += THREADS) s_ctx[i] = 0.0f;

    // Load q into registers: thread's columns are j*128 + lane*4 .. +3, j = 0..7
    float4 qv[VEC];
    float qss = 0.0f;
    const float4* q4 = reinterpret_cast<const float4*>(query);
#pragma unroll
    for (int j = 0; j < VEC; j++) {
        qv[j] = q4[j * 32 + lane];
        qss += qv[j].x * qv[j].x + qv[j].y * qv[j].y
             + qv[j].z * qv[j].z + qv[j].w * qv[j].w;
    }
#pragma unroll
    for (int o = 16; o > 0; o >>= 1)
        qss += __shfl_xor_sync(0xFFFFFFFFu, qss, o);
    const float inv_qn = rsqrtf(qss);

    float acc[VEC * 4];
#pragma unroll
    for (int i = 0; i < VEC * 4; i++) acc[i] = 0.0f;

    const int gw      = blockIdx.x * WARPS + warp;   // global warp id
    const int n_warps = GRID * WARPS;                // 2048

    for (int row = gw; row < S; row += n_warps) {
        const float4* kr = reinterpret_cast<const float4*>(keys + (size_t)row * H);
        float4 kv[VEC];
        float dot = 0.0f, kss = 0.0f;
#pragma unroll
        for (int j = 0; j < VEC; j++) {
            kv[j] = kr[j * 32 + lane];
            dot += qv[j].x * kv[j].x + qv[j].y * kv[j].y
                 + qv[j].z * kv[j].z + qv[j].w * kv[j].w;
            kss += kv[j].x * kv[j].x + kv[j].y * kv[j].y
                 + kv[j].z * kv[j].z + kv[j].w * kv[j].w;
        }
#pragma unroll
        for (int o = 16; o > 0; o >>= 1) {
            dot += __shfl_xor_sync(0xFFFFFFFFu, dot, o);
            kss += __shfl_xor_sync(0xFFFFFFFFu, kss, o);
        }
        const float score = dot * inv_qn * rsqrtf(kss);
#pragma unroll
        for (int j = 0; j < VEC; j++) {
            acc[j * 4 + 0] += score * kv[j].x;
            acc[j * 4 + 1] += score * kv[j].y;
            acc[j * 4 + 2] += score * kv[j].z;
            acc[j * 4 + 3] += score * kv[j].w;
        }
    }

    __syncthreads();   // s_ctx zeroed by all threads before accumulation

    // Per-warp accumulators -> shared context (shared atomics, spread addrs)
#pragma unroll
    for (int j = 0; j < VEC; j++) {
        const int col = j * 128 + lane * 4;
        atomicAdd(&s_ctx[col + 0], acc[j * 4 + 0]);
        atomicAdd(&s_ctx[col + 1], acc[j * 4 + 1]);
        atomicAdd(&s_ctx[col + 2], acc[j * 4 + 2]);
        atomicAdd(&s_ctx[col + 3], acc[j * 4 + 3]);
    }
    __syncthreads();

    // Block partial -> global output
    for (int i = tid; i < H; i += THREADS)
        atomicAdd(&out[i], s_ctx[i]);
}

extern "C" void kernel_launch(void* const* d_in, const int* in_sizes, int n_in,
                              void* d_out, int out_size) {
    const float* query = (const float*)d_in[0];   // [1,1024]
    const float* keys  = (const float*)d_in[1];   // [32768,1024]
    float* out = (float*)d_out;                   // [1,1024]

    zero_out_kernel<<<(H + 255) / 256, 256>>>(out);
    bahdanau_cos_kernel<<<GRID, THREADS>>>(query, keys, out);
}